// round 1
// baseline (speedup 1.0000x reference)
#include <cuda_runtime.h>
#include <math.h>

#define IMG_W 4096
#define IMG_H 4096

// block tiling: block = (32,8) threads, each thread computes TX x TY pixels
#define BX 32
#define BY 8
#define TX 8
#define TY 4
#define GRID_X (IMG_W / (BX * TX))   // 16
#define GRID_Y (IMG_H / (BY * TY))   // 128
#define N_EDGE_BLOCKS (GRID_X * GRID_Y)  // 2048

__device__ float g_edge_partials[N_EDGE_BLOCKS];
__device__ float g_kd_partials[64];

// ---------------------------------------------------------------------------
// row loader: fills s[0..9] = img[row][x0-1 .. x0+8], zero outside image
// ---------------------------------------------------------------------------
__device__ __forceinline__ void load_row(const float* __restrict__ img, int row,
                                         int x0, bool xedge, float s[10]) {
    if ((unsigned)row >= (unsigned)IMG_H) {
#pragma unroll
        for (int i = 0; i < 10; i++) s[i] = 0.0f;
        return;
    }
    const float* p = img + (size_t)row * IMG_W;
    if (!xedge) {
        s[0] = __ldg(p + x0 - 1);
        float4 v0 = __ldg((const float4*)(p + x0));
        float4 v1 = __ldg((const float4*)(p + x0 + 4));
        s[1] = v0.x; s[2] = v0.y; s[3] = v0.z; s[4] = v0.w;
        s[5] = v1.x; s[6] = v1.y; s[7] = v1.z; s[8] = v1.w;
        s[9] = __ldg(p + x0 + 8);
    } else {
#pragma unroll
        for (int i = 0; i < 10; i++) {
            int xx = x0 - 1 + i;
            s[i] = ((unsigned)xx < (unsigned)IMG_W) ? __ldg(p + xx) : 0.0f;
        }
    }
}

__device__ __forceinline__ float warp_reduce_sum(float v) {
#pragma unroll
    for (int off = 16; off > 0; off >>= 1)
        v += __shfl_down_sync(0xFFFFFFFFu, v, off);
    return v;
}

// ---------------------------------------------------------------------------
// main kernel: sum over pixels of (sobel_edge(pred) - sobel_edge(tgt))^2
// ---------------------------------------------------------------------------
__global__ __launch_bounds__(BX * BY)
void edge_loss_kernel(const float* __restrict__ pred, const float* __restrict__ tgt) {
    const int x0 = (blockIdx.x * BX + threadIdx.x) * TX;
    const int y0 = (blockIdx.y * BY + threadIdx.y) * TY;
    const bool xedge = (x0 == 0) || (x0 + TX >= IMG_W);

    float pa[10], pb[10], pc[10];
    float ta[10], tb[10], tc[10];

    load_row(pred, y0 - 1, x0, xedge, pa);
    load_row(tgt,  y0 - 1, x0, xedge, ta);
    load_row(pred, y0,     x0, xedge, pb);
    load_row(tgt,  y0,     x0, xedge, tb);

    float acc = 0.0f;

#pragma unroll
    for (int t = 0; t < TY; t++) {
        const int y = y0 + t;
        load_row(pred, y + 1, x0, xedge, pc);
        load_row(tgt,  y + 1, x0, xedge, tc);

        float pcx[10], pd[10], tcx[10], td[10];
#pragma unroll
        for (int i = 0; i < 10; i++) {
            pcx[i] = pa[i] + 2.0f * pb[i] + pc[i];   // vertical (1,2,1) column sum
            pd[i]  = pc[i] - pa[i];                  // bottom - top
            tcx[i] = ta[i] + 2.0f * tb[i] + tc[i];
            td[i]  = tc[i] - ta[i];
        }
#pragma unroll
        for (int j = 0; j < TX; j++) {
            const int i = j + 1;
            float pex = pcx[i + 1] - pcx[i - 1];
            float pey = pd[i - 1] + 2.0f * pd[i] + pd[i + 1];
            float pe  = sqrtf(pex * pex + pey * pey);
            float gex = tcx[i + 1] - tcx[i - 1];
            float gey = td[i - 1] + 2.0f * td[i] + td[i + 1];
            float te  = sqrtf(gex * gex + gey * gey);
            float df  = pe - te;
            acc += df * df;
        }
#pragma unroll
        for (int i = 0; i < 10; i++) {
            pa[i] = pb[i]; pb[i] = pc[i];
            ta[i] = tb[i]; tb[i] = tc[i];
        }
    }

    // block reduction
    __shared__ float sred[BX * BY / 32];
    float ws = warp_reduce_sum(acc);
    const int lane = threadIdx.x & 31;
    const int wid  = (threadIdx.y * BX + threadIdx.x) >> 5;
    if (lane == 0) sred[wid] = ws;
    __syncthreads();
    if (wid == 0) {
        float v = (lane < (BX * BY / 32)) ? sred[lane] : 0.0f;
        v = warp_reduce_sum(v);
        if (lane == 0)
            g_edge_partials[blockIdx.y * gridDim.x + blockIdx.x] = v;
    }
}

// ---------------------------------------------------------------------------
// keypoint constraint: distance_map = box3x3(pred_edge), bilinear sample
// ---------------------------------------------------------------------------
__device__ __forceinline__ float edge_at(const float* __restrict__ seg, int y, int x) {
    float v[3][3];
#pragma unroll
    for (int dy = 0; dy < 3; dy++)
#pragma unroll
        for (int dx = 0; dx < 3; dx++) {
            int yy = y - 1 + dy, xx = x - 1 + dx;
            v[dy][dx] = ((unsigned)yy < (unsigned)IMG_H && (unsigned)xx < (unsigned)IMG_W)
                        ? __ldg(seg + (size_t)yy * IMG_W + xx) : 0.0f;
        }
    float ex = (v[0][2] + 2.0f * v[1][2] + v[2][2]) - (v[0][0] + 2.0f * v[1][0] + v[2][0]);
    float ey = (v[2][0] + 2.0f * v[2][1] + v[2][2]) - (v[0][0] + 2.0f * v[0][1] + v[0][2]);
    return sqrtf(ex * ex + ey * ey);
}

__global__ __launch_bounds__(256)
void kd_kernel(const float* __restrict__ kp, const float* __restrict__ seg, int K) {
    const int t = blockIdx.x * blockDim.x + threadIdx.x;
    float val = 0.0f;
    if (t < 4 * K) {
        const int k = t >> 2;
        const int c = t & 3;
        float gx = __ldg(kp + 2 * k);
        float gy = __ldg(kp + 2 * k + 1);
        float fx = (gx + 1.0f) * (IMG_W * 0.5f) - 0.5f;
        float fy = (gy + 1.0f) * (IMG_H * 0.5f) - 0.5f;
        float flx = floorf(fx), fly = floorf(fy);
        int x0 = (int)flx, y0 = (int)fly;
        float wx1 = fx - flx, wy1 = fy - fly;
        float wx0 = 1.0f - wx1, wy0 = 1.0f - wy1;
        int cx = x0 + (c & 1);
        int cy = y0 + (c >> 1);
        float w = ((c & 1) ? wx1 : wx0) * ((c >> 1) ? wy1 : wy0);
        if ((unsigned)cx < (unsigned)IMG_W && (unsigned)cy < (unsigned)IMG_H) {
            float dm = 0.0f;
#pragma unroll
            for (int dy = -1; dy <= 1; dy++)
#pragma unroll
                for (int dx = -1; dx <= 1; dx++) {
                    int yy = cy + dy, xx = cx + dx;
                    if ((unsigned)yy < (unsigned)IMG_H && (unsigned)xx < (unsigned)IMG_W)
                        dm += edge_at(seg, yy, xx);
                }
            val = w * dm;
        }
    }
    __shared__ float sred[8];
    float ws = warp_reduce_sum(val);
    const int lane = threadIdx.x & 31;
    const int wid  = threadIdx.x >> 5;
    if (lane == 0) sred[wid] = ws;
    __syncthreads();
    if (wid == 0) {
        float v = (lane < 8) ? sred[lane] : 0.0f;
        v = warp_reduce_sum(v);
        if (lane == 0) g_kd_partials[blockIdx.x] = v;
    }
}

// ---------------------------------------------------------------------------
// finalize: combine partials into the scalar loss
// ---------------------------------------------------------------------------
__global__ __launch_bounds__(256)
void finalize_kernel(float* __restrict__ out, int nEdgeBlocks, int nKdBlocks, int K) {
    float e = 0.0f, kv = 0.0f;
    for (int i = threadIdx.x; i < nEdgeBlocks; i += 256) e += g_edge_partials[i];
    for (int i = threadIdx.x; i < nKdBlocks;  i += 256) kv += g_kd_partials[i];

    __shared__ float se[8], sk[8];
    float we = warp_reduce_sum(e);
    float wk = warp_reduce_sum(kv);
    const int lane = threadIdx.x & 31;
    const int wid  = threadIdx.x >> 5;
    if (lane == 0) { se[wid] = we; sk[wid] = wk; }
    __syncthreads();
    if (wid == 0) {
        float ve = (lane < 8) ? se[lane] : 0.0f;
        float vk = (lane < 8) ? sk[lane] : 0.0f;
        ve = warp_reduce_sum(ve);
        vk = warp_reduce_sum(vk);
        if (lane == 0) {
            float edge_loss = ve * (1.0f / ((float)IMG_W * (float)IMG_H));
            float constraint = vk / (float)K;
            out[0] = 1.0f * edge_loss + 0.5f * constraint;
        }
    }
}

// ---------------------------------------------------------------------------
// launch
// ---------------------------------------------------------------------------
extern "C" void kernel_launch(void* const* d_in, const int* in_sizes, int n_in,
                              void* d_out, int out_size) {
    const float* kp   = (const float*)d_in[0];  // pred_keypoints [K,2]
    // d_in[1] = target_keypoints (unused by reference loss)
    const float* pred = (const float*)d_in[2];  // pred_seg [1,1,4096,4096]
    const float* tgt  = (const float*)d_in[3];  // target_seg

    const int K = in_sizes[0] / 2;

    dim3 blk(BX, BY);
    dim3 grd(GRID_X, GRID_Y);
    edge_loss_kernel<<<grd, blk>>>(pred, tgt);

    const int kdThreads = 4 * K;
    const int kdBlocks  = (kdThreads + 255) / 256;
    kd_kernel<<<kdBlocks, 256>>>(kp, pred, K);

    finalize_kernel<<<1, 256>>>((float*)d_out, GRID_X * GRID_Y, kdBlocks, K);
}

// round 2
// speedup vs baseline: 1.4631x; 1.4631x over previous
#include <cuda_runtime.h>
#include <math.h>

#define IMG_W 4096
#define IMG_H 4096

// edge-loss tiling: 256-thread blocks laid out 32x8; each thread does TX x TY px
#define BX 32
#define BY 8
#define TX 4
#define TY 16
#define GRID_X (IMG_W / (BX * TX))        // 32
#define GRID_Y (IMG_H / (BY * TY))        // 32
#define N_EDGE_BLOCKS (GRID_X * GRID_Y)   // 1024

#define KD_BLOCKS 64                      // 1024 kp * 16 cells / 256

__device__ float g_edge_partials[N_EDGE_BLOCKS];
__device__ float g_kd_partials[KD_BLOCKS];

__device__ __forceinline__ float fsqrt_approx(float x) {
    float r;
    asm("sqrt.approx.f32 %0, %1;" : "=f"(r) : "f"(x));
    return r;
}

__device__ __forceinline__ float warp_reduce_sum(float v) {
#pragma unroll
    for (int off = 16; off > 0; off >>= 1)
        v += __shfl_down_sync(0xFFFFFFFFu, v, off);
    return v;
}

// row loader: s[0..5] = img[row][x0-1 .. x0+4], zero outside image
__device__ __forceinline__ void load_row(const float* __restrict__ img, int row,
                                         int x0, bool xedge, float s[6]) {
    if ((unsigned)row >= (unsigned)IMG_H) {
#pragma unroll
        for (int i = 0; i < 6; i++) s[i] = 0.0f;
        return;
    }
    const float* p = img + (size_t)row * IMG_W;
    if (!xedge) {
        s[0] = __ldg(p + x0 - 1);
        float4 v = __ldg((const float4*)(p + x0));
        s[1] = v.x; s[2] = v.y; s[3] = v.z; s[4] = v.w;
        s[5] = __ldg(p + x0 + 4);
    } else {
#pragma unroll
        for (int i = 0; i < 6; i++) {
            int xx = x0 - 1 + i;
            s[i] = ((unsigned)xx < (unsigned)IMG_W) ? __ldg(p + xx) : 0.0f;
        }
    }
}

// Sobel edge at (y,x) from zero-padded seg
__device__ __forceinline__ float edge_at(const float* __restrict__ seg, int y, int x) {
    float v[3][3];
#pragma unroll
    for (int dy = 0; dy < 3; dy++)
#pragma unroll
        for (int dx = 0; dx < 3; dx++) {
            int yy = y - 1 + dy, xx = x - 1 + dx;
            v[dy][dx] = ((unsigned)yy < (unsigned)IMG_H && (unsigned)xx < (unsigned)IMG_W)
                        ? __ldg(seg + (size_t)yy * IMG_W + xx) : 0.0f;
        }
    float ex = (v[0][2] + 2.0f * v[1][2] + v[2][2]) - (v[0][0] + 2.0f * v[1][0] + v[2][0]);
    float ey = (v[2][0] + 2.0f * v[2][1] + v[2][2]) - (v[0][0] + 2.0f * v[0][1] + v[0][2]);
    return fsqrt_approx(ex * ex + ey * ey);
}

// ---------------------------------------------------------------------------
// fused kernel:
//   blocks [0, KD_BLOCKS)                : keypoint constraint (pred only)
//   blocks [KD_BLOCKS, KD_BLOCKS+NE)     : edge-loss MSE tiles
// ---------------------------------------------------------------------------
__global__ __launch_bounds__(256, 4)
void fused_kernel(const float* __restrict__ pred, const float* __restrict__ tgt,
                  const float* __restrict__ kp, int K) {
    const int tid = threadIdx.x;
    float acc = 0.0f;

    if (blockIdx.x < KD_BLOCKS) {
        // ---- keypoint path: sum over (kp, cell) of W(cell) * edge(cell) ----
        // kd(k) = sum_corners w_c * sum_{|d|inf<=1} edge(c+d)
        //       = sum_{du=-1..2, dv=-1..2} Wx(du)*Wy(dv)*edge(x0+du, y0+dv)
        const int idx = blockIdx.x * 256 + tid;   // [0, 16K)
        const int k    = idx >> 4;
        const int cell = idx & 15;
        if (k < K) {
            float gx = __ldg(kp + 2 * k);
            float gy = __ldg(kp + 2 * k + 1);
            float fx = (gx + 1.0f) * (IMG_W * 0.5f) - 0.5f;
            float fy = (gy + 1.0f) * (IMG_H * 0.5f) - 0.5f;
            float flx = floorf(fx), fly = floorf(fy);
            int x0 = (int)flx, y0 = (int)fly;
            float wx1 = fx - flx, wy1 = fy - fly;
            float wx0 = 1.0f - wx1, wy0 = 1.0f - wy1;
            // corner validity (zero-padding of grid_sample)
            bool vx0 = (unsigned)x0 < (unsigned)IMG_W;
            bool vx1 = (unsigned)(x0 + 1) < (unsigned)IMG_W;
            bool vy0 = (unsigned)y0 < (unsigned)IMG_H;
            bool vy1 = (unsigned)(y0 + 1) < (unsigned)IMG_H;
            float ax0 = vx0 ? wx0 : 0.0f, ax1 = vx1 ? wx1 : 0.0f;
            float ay0 = vy0 ? wy0 : 0.0f, ay1 = vy1 ? wy1 : 0.0f;

            int du = (cell & 3) - 1;     // -1..2
            int dv = (cell >> 2) - 1;    // -1..2
            // Wx(du): corner x0 covers du in {-1,0,1}; corner x0+1 covers {0,1,2}
            float Wx = ((du >= -1 && du <= 1) ? ax0 : 0.0f) + ((du >= 0) ? ax1 : 0.0f);
            float Wy = ((dv >= -1 && dv <= 1) ? ay0 : 0.0f) + ((dv >= 0) ? ay1 : 0.0f);
            float W = Wx * Wy;
            int cx = x0 + du, cy = y0 + dv;
            if (W != 0.0f && (unsigned)cx < (unsigned)IMG_W && (unsigned)cy < (unsigned)IMG_H)
                acc = W * edge_at(pred, cy, cx);
        }
        // block reduce -> kd partial
        __shared__ float sred[8];
        float ws = warp_reduce_sum(acc);
        int lane = tid & 31, wid = tid >> 5;
        if (lane == 0) sred[wid] = ws;
        __syncthreads();
        if (wid == 0) {
            float v = (lane < 8) ? sred[lane] : 0.0f;
            v = warp_reduce_sum(v);
            if (lane == 0) g_kd_partials[blockIdx.x] = v;
        }
        return;
    }

    // ---- edge-loss path ----
    const int bid = blockIdx.x - KD_BLOCKS;
    const int bx = bid % GRID_X;
    const int by = bid / GRID_X;
    const int lx = tid & 31;          // 0..31
    const int ly = tid >> 5;          // 0..7
    const int x0 = (bx * BX + lx) * TX;
    const int y0 = (by * BY + ly) * TY;
    const bool xedge = (x0 == 0) || (x0 + TX >= IMG_W);

    float P[3][6], T[3][6];
    load_row(pred, y0 - 1, x0, xedge, P[0]);
    load_row(tgt,  y0 - 1, x0, xedge, T[0]);
    load_row(pred, y0,     x0, xedge, P[1]);
    load_row(tgt,  y0,     x0, xedge, T[1]);

#pragma unroll
    for (int t = 0; t < TY; t++) {
        const int am = t % 3, bm = (t + 1) % 3, cm = (t + 2) % 3;
        load_row(pred, y0 + t + 1, x0, xedge, P[cm]);
        load_row(tgt,  y0 + t + 1, x0, xedge, T[cm]);

        const float* pa = P[am]; const float* pb = P[bm]; const float* pc = P[cm];
        const float* ta = T[am]; const float* tb = T[bm]; const float* tc = T[cm];
#pragma unroll
        for (int j = 0; j < TX; j++) {
            float pex = (pa[j + 2] + 2.0f * pb[j + 2] + pc[j + 2])
                      - (pa[j]     + 2.0f * pb[j]     + pc[j]);
            float pey = (pc[j] - pa[j]) + 2.0f * (pc[j + 1] - pa[j + 1]) + (pc[j + 2] - pa[j + 2]);
            float pe  = fsqrt_approx(pex * pex + pey * pey);
            float tex = (ta[j + 2] + 2.0f * tb[j + 2] + tc[j + 2])
                      - (ta[j]     + 2.0f * tb[j]     + tc[j]);
            float tey = (tc[j] - ta[j]) + 2.0f * (tc[j + 1] - ta[j + 1]) + (tc[j + 2] - ta[j + 2]);
            float te  = fsqrt_approx(tex * tex + tey * tey);
            float df  = pe - te;
            acc += df * df;
        }
    }

    __shared__ float sred[8];
    float ws = warp_reduce_sum(acc);
    int lane = tid & 31, wid = tid >> 5;
    if (lane == 0) sred[wid] = ws;
    __syncthreads();
    if (wid == 0) {
        float v = (lane < 8) ? sred[lane] : 0.0f;
        v = warp_reduce_sum(v);
        if (lane == 0) g_edge_partials[bid] = v;
    }
}

// ---------------------------------------------------------------------------
// finalize: combine partials into the scalar loss
// ---------------------------------------------------------------------------
__global__ __launch_bounds__(256)
void finalize_kernel(float* __restrict__ out, int K) {
    float e = 0.0f, kv = 0.0f;
    for (int i = threadIdx.x; i < N_EDGE_BLOCKS; i += 256) e += g_edge_partials[i];
    if (threadIdx.x < KD_BLOCKS) kv = g_kd_partials[threadIdx.x];

    __shared__ float se[8], sk[8];
    float we = warp_reduce_sum(e);
    float wk = warp_reduce_sum(kv);
    const int lane = threadIdx.x & 31;
    const int wid  = threadIdx.x >> 5;
    if (lane == 0) { se[wid] = we; sk[wid] = wk; }
    __syncthreads();
    if (wid == 0) {
        float ve = (lane < 8) ? se[lane] : 0.0f;
        float vk = (lane < 8) ? sk[lane] : 0.0f;
        ve = warp_reduce_sum(ve);
        vk = warp_reduce_sum(vk);
        if (lane == 0) {
            float edge_loss = ve * (1.0f / ((float)IMG_W * (float)IMG_H));
            float constraint = vk / (float)K;
            out[0] = 1.0f * edge_loss + 0.5f * constraint;
        }
    }
}

// ---------------------------------------------------------------------------
extern "C" void kernel_launch(void* const* d_in, const int* in_sizes, int n_in,
                              void* d_out, int out_size) {
    const float* kp   = (const float*)d_in[0];  // pred_keypoints [K,2]
    const float* pred = (const float*)d_in[2];  // pred_seg
    const float* tgt  = (const float*)d_in[3];  // target_seg
    const int K = in_sizes[0] / 2;

    fused_kernel<<<KD_BLOCKS + N_EDGE_BLOCKS, 256>>>(pred, tgt, kp, K);
    finalize_kernel<<<1, 256>>>((float*)d_out, K);
}

// round 3
// speedup vs baseline: 1.4706x; 1.0051x over previous
#include <cuda_runtime.h>
#include <math.h>

#define IMG_W 4096
#define IMG_H 4096

// edge-loss tiling: 256-thread blocks laid out 32x8; each thread does TX x TY px
#define BX 32
#define BY 8
#define TX 4
#define TY 16
#define GRID_X (IMG_W / (BX * TX))        // 32
#define GRID_Y (IMG_H / (BY * TY))        // 32
#define N_EDGE_BLOCKS (GRID_X * GRID_Y)   // 1024

#define KD_BLOCKS 64                      // 1024 kp * 16 cells / 256
#define TOTAL_BLOCKS (KD_BLOCKS + N_EDGE_BLOCKS)

__device__ float g_edge_partials[N_EDGE_BLOCKS];
__device__ float g_kd_partials[KD_BLOCKS];
__device__ unsigned int g_done_count;     // zero-initialized; reset by last block

__device__ __forceinline__ float fsqrt_approx(float x) {
    float r;
    asm("sqrt.approx.f32 %0, %1;" : "=f"(r) : "f"(x));
    return r;
}

__device__ __forceinline__ float warp_reduce_sum(float v) {
#pragma unroll
    for (int off = 16; off > 0; off >>= 1)
        v += __shfl_down_sync(0xFFFFFFFFu, v, off);
    return v;
}

// row loader: s[0..5] = img[row][x0-1 .. x0+4], zero outside image
__device__ __forceinline__ void load_row(const float* __restrict__ img, int row,
                                         int x0, bool xedge, float s[6]) {
    if ((unsigned)row >= (unsigned)IMG_H) {
#pragma unroll
        for (int i = 0; i < 6; i++) s[i] = 0.0f;
        return;
    }
    const float* p = img + (size_t)row * IMG_W;
    if (!xedge) {
        s[0] = __ldg(p + x0 - 1);
        float4 v = __ldg((const float4*)(p + x0));
        s[1] = v.x; s[2] = v.y; s[3] = v.z; s[4] = v.w;
        s[5] = __ldg(p + x0 + 4);
    } else {
#pragma unroll
        for (int i = 0; i < 6; i++) {
            int xx = x0 - 1 + i;
            s[i] = ((unsigned)xx < (unsigned)IMG_W) ? __ldg(p + xx) : 0.0f;
        }
    }
}

// Sobel edge at (y,x) from zero-padded seg
__device__ __forceinline__ float edge_at(const float* __restrict__ seg, int y, int x) {
    float v[3][3];
#pragma unroll
    for (int dy = 0; dy < 3; dy++)
#pragma unroll
        for (int dx = 0; dx < 3; dx++) {
            int yy = y - 1 + dy, xx = x - 1 + dx;
            v[dy][dx] = ((unsigned)yy < (unsigned)IMG_H && (unsigned)xx < (unsigned)IMG_W)
                        ? __ldg(seg + (size_t)yy * IMG_W + xx) : 0.0f;
        }
    float ex = (v[0][2] + 2.0f * v[1][2] + v[2][2]) - (v[0][0] + 2.0f * v[1][0] + v[2][0]);
    float ey = (v[2][0] + 2.0f * v[2][1] + v[2][2]) - (v[0][0] + 2.0f * v[0][1] + v[0][2]);
    return fsqrt_approx(ex * ex + ey * ey);
}

// ---------------------------------------------------------------------------
// fused kernel:
//   blocks [0, KD_BLOCKS)            : keypoint constraint (pred only)
//   blocks [KD_BLOCKS, TOTAL_BLOCKS) : edge-loss MSE tiles
//   last block to finish             : grid-wide reduction -> out[0]
// ---------------------------------------------------------------------------
__global__ __launch_bounds__(256, 4)
void fused_kernel(const float* __restrict__ pred, const float* __restrict__ tgt,
                  const float* __restrict__ kp, int K, float* __restrict__ out) {
    const int tid = threadIdx.x;
    float acc = 0.0f;
    __shared__ float sred[8];
    __shared__ bool s_last;

    if (blockIdx.x < KD_BLOCKS) {
        // ---- keypoint path ----
        // kd(k) = sum_{du,dv in -1..2} Wx(du)*Wy(dv)*edge(x0+du, y0+dv)
        const int idx = blockIdx.x * 256 + tid;   // [0, 16K)
        const int k    = idx >> 4;
        const int cell = idx & 15;
        if (k < K) {
            float gx = __ldg(kp + 2 * k);
            float gy = __ldg(kp + 2 * k + 1);
            float fx = (gx + 1.0f) * (IMG_W * 0.5f) - 0.5f;
            float fy = (gy + 1.0f) * (IMG_H * 0.5f) - 0.5f;
            float flx = floorf(fx), fly = floorf(fy);
            int x0 = (int)flx, y0 = (int)fly;
            float wx1 = fx - flx, wy1 = fy - fly;
            float wx0 = 1.0f - wx1, wy0 = 1.0f - wy1;
            bool vx0 = (unsigned)x0 < (unsigned)IMG_W;
            bool vx1 = (unsigned)(x0 + 1) < (unsigned)IMG_W;
            bool vy0 = (unsigned)y0 < (unsigned)IMG_H;
            bool vy1 = (unsigned)(y0 + 1) < (unsigned)IMG_H;
            float ax0 = vx0 ? wx0 : 0.0f, ax1 = vx1 ? wx1 : 0.0f;
            float ay0 = vy0 ? wy0 : 0.0f, ay1 = vy1 ? wy1 : 0.0f;

            int du = (cell & 3) - 1;     // -1..2
            int dv = (cell >> 2) - 1;    // -1..2
            float Wx = ((du <= 1) ? ax0 : 0.0f) + ((du >= 0) ? ax1 : 0.0f);
            float Wy = ((dv <= 1) ? ay0 : 0.0f) + ((dv >= 0) ? ay1 : 0.0f);
            float W = Wx * Wy;
            int cx = x0 + du, cy = y0 + dv;
            if (W != 0.0f && (unsigned)cx < (unsigned)IMG_W && (unsigned)cy < (unsigned)IMG_H)
                acc = W * edge_at(pred, cy, cx);
        }
        float ws = warp_reduce_sum(acc);
        int lane = tid & 31, wid = tid >> 5;
        if (lane == 0) sred[wid] = ws;
        __syncthreads();
        if (wid == 0) {
            float v = (lane < 8) ? sred[lane] : 0.0f;
            v = warp_reduce_sum(v);
            if (lane == 0) g_kd_partials[blockIdx.x] = v;
        }
    } else {
        // ---- edge-loss path ----
        const int bid = blockIdx.x - KD_BLOCKS;
        const int bx = bid % GRID_X;
        const int by = bid / GRID_X;
        const int lx = tid & 31;
        const int ly = tid >> 5;
        const int x0 = (bx * BX + lx) * TX;
        const int y0 = (by * BY + ly) * TY;
        const bool xedge = (x0 == 0) || (x0 + TX >= IMG_W);

        float P[3][6], T[3][6];
        load_row(pred, y0 - 1, x0, xedge, P[0]);
        load_row(tgt,  y0 - 1, x0, xedge, T[0]);
        load_row(pred, y0,     x0, xedge, P[1]);
        load_row(tgt,  y0,     x0, xedge, T[1]);

#pragma unroll
        for (int t = 0; t < TY; t++) {
            const int am = t % 3, bm = (t + 1) % 3, cm = (t + 2) % 3;
            load_row(pred, y0 + t + 1, x0, xedge, P[cm]);
            load_row(tgt,  y0 + t + 1, x0, xedge, T[cm]);

            const float* pa = P[am]; const float* pb = P[bm]; const float* pc = P[cm];
            const float* ta = T[am]; const float* tb = T[bm]; const float* tc = T[cm];
#pragma unroll
            for (int j = 0; j < TX; j++) {
                float pex = (pa[j + 2] + 2.0f * pb[j + 2] + pc[j + 2])
                          - (pa[j]     + 2.0f * pb[j]     + pc[j]);
                float pey = (pc[j] - pa[j]) + 2.0f * (pc[j + 1] - pa[j + 1]) + (pc[j + 2] - pa[j + 2]);
                float pe  = fsqrt_approx(pex * pex + pey * pey);
                float tex = (ta[j + 2] + 2.0f * tb[j + 2] + tc[j + 2])
                          - (ta[j]     + 2.0f * tb[j]     + tc[j]);
                float tey = (tc[j] - ta[j]) + 2.0f * (tc[j + 1] - ta[j + 1]) + (tc[j + 2] - ta[j + 2]);
                float te  = fsqrt_approx(tex * tex + tey * tey);
                float df  = pe - te;
                acc += df * df;
            }
        }

        float ws = warp_reduce_sum(acc);
        int lane = tid & 31, wid = tid >> 5;
        if (lane == 0) sred[wid] = ws;
        __syncthreads();
        if (wid == 0) {
            float v = (lane < 8) ? sred[lane] : 0.0f;
            v = warp_reduce_sum(v);
            if (lane == 0) g_edge_partials[bid] = v;
        }
    }

    // ---- grid-wide completion detection; last block reduces everything ----
    __threadfence();
    if (tid == 0) {
        unsigned int prev = atomicAdd(&g_done_count, 1u);
        s_last = (prev == TOTAL_BLOCKS - 1);
    }
    __syncthreads();
    if (!s_last) return;

    // last block: deterministic fixed-order reduction of all partials
    float e = 0.0f, kv = 0.0f;
    for (int i = tid; i < N_EDGE_BLOCKS; i += 256) e += g_edge_partials[i];
    if (tid < KD_BLOCKS) kv = g_kd_partials[tid];

    __shared__ float se[8], sk[8];
    float we = warp_reduce_sum(e);
    float wk = warp_reduce_sum(kv);
    const int lane = tid & 31;
    const int wid  = tid >> 5;
    if (lane == 0) { se[wid] = we; sk[wid] = wk; }
    __syncthreads();
    if (wid == 0) {
        float ve = (lane < 8) ? se[lane] : 0.0f;
        float vk = (lane < 8) ? sk[lane] : 0.0f;
        ve = warp_reduce_sum(ve);
        vk = warp_reduce_sum(vk);
        if (lane == 0) {
            float edge_loss = ve * (1.0f / ((float)IMG_W * (float)IMG_H));
            float constraint = vk / (float)K;
            out[0] = 1.0f * edge_loss + 0.5f * constraint;
            g_done_count = 0;   // reset for next graph replay
        }
    }
}

// ---------------------------------------------------------------------------
extern "C" void kernel_launch(void* const* d_in, const int* in_sizes, int n_in,
                              void* d_out, int out_size) {
    const float* kp   = (const float*)d_in[0];  // pred_keypoints [K,2]
    const float* pred = (const float*)d_in[2];  // pred_seg
    const float* tgt  = (const float*)d_in[3];  // target_seg
    const int K = in_sizes[0] / 2;

    fused_kernel<<<TOTAL_BLOCKS, 256>>>(pred, tgt, kp, K, (float*)d_out);
}